// round 2
// baseline (speedup 1.0000x reference)
#include <cuda_runtime.h>
#include <cuda_bf16.h>

// Problem constants (fixed by the dataset)
#define T_TOK 16384
#define DDIM  1024
#define NEXP  8

// Per-expert compaction lists (scratch via __device__ globals per harness rules)
__device__ int   g_count[NEXP];
__device__ int   g_tok [NEXP][T_TOK];
__device__ float g_gate[NEXP][T_TOK];

// ---------------------------------------------------------------------------
// Kernel 0: zero output + expert counters
// ---------------------------------------------------------------------------
__global__ void zero_kernel(float* __restrict__ out) {
    int i = blockIdx.x * blockDim.x + threadIdx.x;
    int n4 = (T_TOK * DDIM) / 4;
    if (i < n4) reinterpret_cast<float4*>(out)[i] = make_float4(0.f, 0.f, 0.f, 0.f);
    if (blockIdx.x == 0 && threadIdx.x < NEXP) g_count[threadIdx.x] = 0;
}

// ---------------------------------------------------------------------------
// Kernel 1: gating. fp32 logits, exact top-2 (lowest-index tie-break like
// jax.lax.top_k), softmax over the 2, compact tokens into per-expert lists.
// One warp per token, Wg staged in smem.
// ---------------------------------------------------------------------------
__global__ void gate_kernel(const float* __restrict__ x,
                            const float* __restrict__ Wg,
                            const float* __restrict__ bg) {
    __shared__ float sWg[NEXP * DDIM];
    int tid = threadIdx.x;                       // 256 threads
    for (int i = tid; i < NEXP * DDIM; i += 256) sWg[i] = Wg[i];
    __syncthreads();

    int warp = tid >> 5, lane = tid & 31;
    int t = blockIdx.x * 8 + warp;
    if (t >= T_TOK) return;

    const float4* xr = reinterpret_cast<const float4*>(x + (size_t)t * DDIM);
    float acc[NEXP];
#pragma unroll
    for (int e = 0; e < NEXP; e++) acc[e] = 0.f;

#pragma unroll
    for (int j = 0; j < 8; j++) {                // 8 float4 per lane covers D=1024
        float4 xv = xr[j * 32 + lane];
#pragma unroll
        for (int e = 0; e < NEXP; e++) {
            float4 wv = reinterpret_cast<const float4*>(sWg + e * DDIM)[j * 32 + lane];
            acc[e] += xv.x * wv.x + xv.y * wv.y + xv.z * wv.z + xv.w * wv.w;
        }
    }
#pragma unroll
    for (int off = 16; off > 0; off >>= 1)
#pragma unroll
        for (int e = 0; e < NEXP; e++)
            acc[e] += __shfl_xor_sync(0xFFFFFFFFu, acc[e], off);

    if (lane == 0) {
        float l[NEXP];
#pragma unroll
        for (int e = 0; e < NEXP; e++) l[e] = acc[e] + bg[e];
        int i0 = 0;
#pragma unroll
        for (int e = 1; e < NEXP; e++) if (l[e] > l[i0]) i0 = e;
        int i1 = -1;
#pragma unroll
        for (int e = 0; e < NEXP; e++) {
            if (e == i0) continue;
            if (i1 < 0 || l[e] > l[i1]) i1 = e;
        }
        float m  = fmaxf(l[i0], l[i1]);
        float e0 = __expf(l[i0] - m);
        float e1 = __expf(l[i1] - m);
        float inv = 1.f / (e0 + e1);
        float g0 = e0 * inv, g1 = e1 * inv;

        int p0 = atomicAdd(&g_count[i0], 1);
        g_tok[i0][p0] = t; g_gate[i0][p0] = g0;
        int p1 = atomicAdd(&g_count[i1], 1);
        g_tok[i1][p1] = t; g_gate[i1][p1] = g1;
    }
}

// ---------------------------------------------------------------------------
// Kernel 2: per-expert gathered SGEMM, 128x128 tile, BK=8, 256 threads,
// 8x8 micro-tile per thread. Epilogue: out[tok] += g * (acc + be[e]).
// Grid: (n_tiles=8, m_tiles=128, experts=8); empty tiles early-exit.
// ---------------------------------------------------------------------------
__global__ void __launch_bounds__(256, 2)
expert_gemm_kernel(const float* __restrict__ x,
                   const float* __restrict__ We,
                   const float* __restrict__ be,
                   float* __restrict__ out) {
    const int e = blockIdx.z;
    const int cnt = g_count[e];
    const int m0 = blockIdx.y * 128;
    if (m0 >= cnt) return;
    const int n0 = blockIdx.x * 128;

    __shared__ float Xs[8][132];
    __shared__ float Ws[8][132];

    const int tid = threadIdx.x;
    const int lm = tid >> 1;               // 0..127: which tile row I stage
    const int lk = (tid & 1) * 4;          // k sub-offset (0 or 4)

    // Gathered X row for staging
    int tok_ld = -1;
    if (m0 + lm < cnt) tok_ld = g_tok[e][m0 + lm];
    const float* xrow = (tok_ld >= 0) ? (x + (size_t)tok_ld * DDIM) : x;
    const float* wrow = We + (size_t)e * DDIM * DDIM + (size_t)(n0 + lm) * DDIM;

    float acc[8][8];
#pragma unroll
    for (int i = 0; i < 8; i++)
#pragma unroll
        for (int j = 0; j < 8; j++) acc[i][j] = 0.f;

    const int tr = (tid >> 4) * 8;         // my 8 output rows within tile
    const int tc = (tid & 15) * 8;         // my 8 output cols within tile

    // software pipeline: preload k-tile 0
    float4 av = make_float4(0.f, 0.f, 0.f, 0.f);
    if (tok_ld >= 0) av = *reinterpret_cast<const float4*>(xrow + lk);
    float4 bv = *reinterpret_cast<const float4*>(wrow + lk);

    for (int k0 = 0; k0 < DDIM; k0 += 8) {
        __syncthreads();
        Xs[lk + 0][lm] = av.x; Xs[lk + 1][lm] = av.y;
        Xs[lk + 2][lm] = av.z; Xs[lk + 3][lm] = av.w;
        Ws[lk + 0][lm] = bv.x; Ws[lk + 1][lm] = bv.y;
        Ws[lk + 2][lm] = bv.z; Ws[lk + 3][lm] = bv.w;
        __syncthreads();

        if (k0 + 8 < DDIM) {
            if (tok_ld >= 0) av = *reinterpret_cast<const float4*>(xrow + k0 + 8 + lk);
            bv = *reinterpret_cast<const float4*>(wrow + k0 + 8 + lk);
        }

#pragma unroll
        for (int k = 0; k < 8; k++) {
            float a[8], b[8];
            float4 a0 = *reinterpret_cast<const float4*>(&Xs[k][tr]);
            float4 a1 = *reinterpret_cast<const float4*>(&Xs[k][tr + 4]);
            float4 b0 = *reinterpret_cast<const float4*>(&Ws[k][tc]);
            float4 b1 = *reinterpret_cast<const float4*>(&Ws[k][tc + 4]);
            a[0]=a0.x; a[1]=a0.y; a[2]=a0.z; a[3]=a0.w;
            a[4]=a1.x; a[5]=a1.y; a[6]=a1.z; a[7]=a1.w;
            b[0]=b0.x; b[1]=b0.y; b[2]=b0.z; b[3]=b0.w;
            b[4]=b1.x; b[5]=b1.y; b[6]=b1.z; b[7]=b1.w;
#pragma unroll
            for (int i = 0; i < 8; i++)
#pragma unroll
                for (int j = 0; j < 8; j++)
                    acc[i][j] = fmaf(a[i], b[j], acc[i][j]);
        }
    }

    // Epilogue: out[tok] += g * (acc + be)
    const float* berow = be + e * DDIM + n0 + tc;
#pragma unroll
    for (int i = 0; i < 8; i++) {
        int m = m0 + tr + i;
        if (m >= cnt) continue;
        int tok = g_tok[e][m];
        float g = g_gate[e][m];
        float* orow = out + (size_t)tok * DDIM + n0 + tc;
#pragma unroll
        for (int j = 0; j < 8; j++)
            atomicAdd(&orow[j], g * (acc[i][j] + berow[j]));
    }
}

// ---------------------------------------------------------------------------
extern "C" void kernel_launch(void* const* d_in, const int* in_sizes, int n_in,
                              void* d_out, int out_size) {
    const float* x  = (const float*)d_in[0];   // [16384, 1024]
    const float* Wg = (const float*)d_in[1];   // [8, 1024]
    const float* bg = (const float*)d_in[2];   // [8]
    const float* We = (const float*)d_in[3];   // [8, 1024, 1024]
    const float* be = (const float*)d_in[4];   // [8, 1024]
    float* out = (float*)d_out;                // [16384, 1024]

    int n4 = (T_TOK * DDIM) / 4;
    zero_kernel<<<(n4 + 255) / 256, 256>>>(out);

    gate_kernel<<<T_TOK / 8, 256>>>(x, Wg, bg);

    dim3 grid(DDIM / 128, T_TOK / 128, NEXP);  // (n-tiles, m-tiles, experts)
    expert_gemm_kernel<<<grid, 256>>>(x, We, be, out);
}

// round 4
// speedup vs baseline: 6.4697x; 6.4697x over previous
#include <cuda_runtime.h>
#include <cuda_fp16.h>
#include <cstdint>

// Problem constants (fixed by the dataset)
#define T_TOK 16384
#define DDIM  1024
#define NEXP  8

// GEMM tiling
#define MT  128
#define NT  128
#define KC  64
#define NCH (DDIM / KC)        // 16 k-chunks
#define STAGE_B 32768          // A(16KB) + B(16KB) per stage
#define SMEM_DYN (2 * STAGE_B) // 64KB

// ---------------------------------------------------------------------------
// Scratch (device globals; allocation is forbidden)
// ---------------------------------------------------------------------------
__device__ int   g_count[NEXP];
__device__ int   g_tok [NEXP][T_TOK];
__device__ float g_gate[NEXP][T_TOK];
__device__ __half g_xf[(size_t)T_TOK * DDIM];             // x in fp16
__device__ __half g_wf[(size_t)NEXP * DDIM * DDIM];       // We in fp16

// ---------------------------------------------------------------------------
// PTX helpers (base-ISA only: works on plain sm_103 target)
// ---------------------------------------------------------------------------
__device__ __forceinline__ uint32_t smem_u32(const void* p) {
    uint32_t a;
    asm("{ .reg .u64 t; cvta.to.shared.u64 t, %1; cvt.u32.u64 %0, t; }" : "=r"(a) : "l"(p));
    return a;
}
__device__ __forceinline__ uint32_t swz(uint32_t o) { return o ^ ((o >> 3) & 0x70); }

__device__ __forceinline__ void cp16(uint32_t dst, const void* src) {
    asm volatile("cp.async.cg.shared.global [%0], [%1], 16;" :: "r"(dst), "l"(src));
}
#define CP_COMMIT() asm volatile("cp.async.commit_group;" ::: "memory")
#define CP_WAIT(n)  asm volatile("cp.async.wait_group %0;" :: "n"(n) : "memory")

__device__ __forceinline__ void ldmx4(uint32_t* r, uint32_t addr) {
    asm volatile("ldmatrix.sync.aligned.m8n8.x4.shared.b16 {%0,%1,%2,%3}, [%4];"
                 : "=r"(r[0]), "=r"(r[1]), "=r"(r[2]), "=r"(r[3]) : "r"(addr));
}

__device__ __forceinline__ void mma16816(float* c, const uint32_t* a, const uint32_t* b) {
    asm volatile("mma.sync.aligned.m16n8k16.row.col.f32.f16.f16.f32 "
                 "{%0,%1,%2,%3}, {%4,%5,%6,%7}, {%8,%9}, {%0,%1,%2,%3};"
                 : "+f"(c[0]), "+f"(c[1]), "+f"(c[2]), "+f"(c[3])
                 : "r"(a[0]), "r"(a[1]), "r"(a[2]), "r"(a[3]), "r"(b[0]), "r"(b[1]));
}

__device__ __forceinline__ void red_v2(float* p, float v0, float v1) {
    asm volatile("red.global.add.v2.f32 [%0], {%1, %2};" :: "l"(p), "f"(v0), "f"(v1) : "memory");
}

// ---------------------------------------------------------------------------
// Kernel 0: zero output + counters
// ---------------------------------------------------------------------------
__global__ void zero_kernel(float* __restrict__ out) {
    int i = blockIdx.x * blockDim.x + threadIdx.x;     // grid exactly covers n4
    reinterpret_cast<float4*>(out)[i] = make_float4(0.f, 0.f, 0.f, 0.f);
    if (blockIdx.x == 0 && threadIdx.x < NEXP) g_count[threadIdx.x] = 0;
}

// ---------------------------------------------------------------------------
// Kernel 0b: fp32 -> fp16 conversions
// ---------------------------------------------------------------------------
__global__ void cvt_x_kernel(const float* __restrict__ x) {
    int i = blockIdx.x * blockDim.x + threadIdx.x;     // float4 index
    float4 v = reinterpret_cast<const float4*>(x)[i];
    __half2* d = reinterpret_cast<__half2*>(g_xf);
    d[i * 2 + 0] = __floats2half2_rn(v.x, v.y);
    d[i * 2 + 1] = __floats2half2_rn(v.z, v.w);
}
__global__ void cvt_w_kernel(const float* __restrict__ w) {
    int i = blockIdx.x * blockDim.x + threadIdx.x;
    float4 v = reinterpret_cast<const float4*>(w)[i];
    __half2* d = reinterpret_cast<__half2*>(g_wf);
    d[i * 2 + 0] = __floats2half2_rn(v.x, v.y);
    d[i * 2 + 1] = __floats2half2_rn(v.z, v.w);
}

// ---------------------------------------------------------------------------
// Kernel 1: gating (fp32-exact top-2 + softmax + compaction)
// ---------------------------------------------------------------------------
__global__ void gate_kernel(const float* __restrict__ x,
                            const float* __restrict__ Wg,
                            const float* __restrict__ bg) {
    __shared__ float sWg[NEXP * DDIM];
    int tid = threadIdx.x;
    for (int i = tid; i < NEXP * DDIM; i += 256) sWg[i] = Wg[i];
    __syncthreads();

    int warp = tid >> 5, lane = tid & 31;
    int t = blockIdx.x * 8 + warp;
    if (t >= T_TOK) return;

    const float4* xr = reinterpret_cast<const float4*>(x + (size_t)t * DDIM);
    float acc[NEXP];
#pragma unroll
    for (int e = 0; e < NEXP; e++) acc[e] = 0.f;
#pragma unroll
    for (int j = 0; j < 8; j++) {
        float4 xv = xr[j * 32 + lane];
#pragma unroll
        for (int e = 0; e < NEXP; e++) {
            float4 wv = reinterpret_cast<const float4*>(sWg + e * DDIM)[j * 32 + lane];
            acc[e] += xv.x * wv.x + xv.y * wv.y + xv.z * wv.z + xv.w * wv.w;
        }
    }
#pragma unroll
    for (int off = 16; off > 0; off >>= 1)
#pragma unroll
        for (int e = 0; e < NEXP; e++)
            acc[e] += __shfl_xor_sync(0xFFFFFFFFu, acc[e], off);

    if (lane == 0) {
        float l[NEXP];
#pragma unroll
        for (int e = 0; e < NEXP; e++) l[e] = acc[e] + bg[e];
        int i0 = 0;
#pragma unroll
        for (int e = 1; e < NEXP; e++) if (l[e] > l[i0]) i0 = e;
        int i1 = -1;
#pragma unroll
        for (int e = 0; e < NEXP; e++) {
            if (e == i0) continue;
            if (i1 < 0 || l[e] > l[i1]) i1 = e;
        }
        float m  = fmaxf(l[i0], l[i1]);
        float e0 = __expf(l[i0] - m);
        float e1 = __expf(l[i1] - m);
        float inv = 1.f / (e0 + e1);

        int p0 = atomicAdd(&g_count[i0], 1);
        g_tok[i0][p0] = t; g_gate[i0][p0] = e0 * inv;
        int p1 = atomicAdd(&g_count[i1], 1);
        g_tok[i1][p1] = t; g_gate[i1][p1] = e1 * inv;
    }
}

// ---------------------------------------------------------------------------
// Kernel 2: fp16 HMMA expert GEMM (mma.sync.m16n8k16), 128x128 tile,
// 2-stage cp.async pipeline, swizzled smem + ldmatrix.
// Epilogue: out[tok] += g * (acc + be[e]) via red.global.add.v2.f32
// ---------------------------------------------------------------------------
__global__ void __launch_bounds__(256, 2)
moe_gemm_kernel(const float* __restrict__ be, float* __restrict__ out) {
    const int e   = blockIdx.z;
    const int cnt = g_count[e];
    const int m0  = blockIdx.y * MT;
    if (m0 >= cnt) return;
    const int n0  = blockIdx.x * NT;

    extern __shared__ __align__(128) char smem[];
    const uint32_t sbase = smem_u32(smem);

    __shared__ int   s_tok[MT];
    __shared__ float s_gate[MT];

    const int tid  = threadIdx.x;
    const int wid  = tid >> 5, lane = tid & 31;
    const int wm   = (wid & 3) * 32;     // warp row offset in tile
    const int wn   = (wid >> 2) * 64;    // warp col offset in tile

    if (tid < MT) {
        int m = m0 + tid;
        s_tok[tid]  = (m < cnt) ? g_tok[e][m]  : 0;
        s_gate[tid] = (m < cnt) ? g_gate[e][m] : 0.f;
    }
    __syncthreads();

    const size_t wbase = ((size_t)e << 20) + (size_t)n0 * DDIM;  // e*1024*1024

    // --- stage loader: A rows gathered via s_tok, B rows from We[e] ---
    auto load_stage = [&](int ck, int s) {
        const int k0 = ck * KC;
        const uint32_t sA = sbase + s * STAGE_B;
        const uint32_t sB = sA + 16384;
#pragma unroll
        for (int i = 0; i < 4; i++) {
            int u = tid + i * 256;               // 0..1023
            int row = u >> 3, c = u & 7;         // 128 rows x 8 16B-chunks
            const __half* src = &g_xf[(size_t)s_tok[row] * DDIM + k0 + c * 8];
            cp16(sA + swz((uint32_t)(row * 128 + c * 16)), src);
        }
#pragma unroll
        for (int i = 0; i < 4; i++) {
            int u = tid + i * 256;
            int row = u >> 3, c = u & 7;
            const __half* src = &g_wf[wbase + (size_t)row * DDIM + k0 + c * 8];
            cp16(sB + swz((uint32_t)(row * 128 + c * 16)), src);
        }
        CP_COMMIT();
    };

    float acc[2][8][4];
#pragma unroll
    for (int mi = 0; mi < 2; mi++)
#pragma unroll
        for (int ni = 0; ni < 8; ni++)
#pragma unroll
            for (int q = 0; q < 4; q++) acc[mi][ni][q] = 0.f;

    load_stage(0, 0);
    load_stage(1, 1);

#pragma unroll 1
    for (int ck = 0; ck < NCH; ck++) {
        if (ck + 1 < NCH) { CP_WAIT(1); } else { CP_WAIT(0); }
        __syncthreads();

        const uint32_t sA = sbase + (ck & 1) * STAGE_B;
        const uint32_t sB = sA + 16384;

#pragma unroll
        for (int ks = 0; ks < 4; ks++) {
            uint32_t a[2][4];
#pragma unroll
            for (int mi = 0; mi < 2; mi++) {
                int row = wm + mi * 16 + (lane & 15);
                ldmx4(a[mi], sA + swz((uint32_t)(row * 128 + (ks * 2 + (lane >> 4)) * 16)));
            }
            uint32_t b[4][4];
#pragma unroll
            for (int pi = 0; pi < 4; pi++) {
                int n = wn + pi * 16 + ((lane >> 4) << 3) + (lane & 7);
                ldmx4(b[pi], sB + swz((uint32_t)(n * 128 + (ks * 2 + ((lane >> 3) & 1)) * 16)));
            }
#pragma unroll
            for (int mi = 0; mi < 2; mi++)
#pragma unroll
                for (int ni = 0; ni < 8; ni++)
                    mma16816(acc[mi][ni], a[mi], &b[ni >> 1][(ni & 1) * 2]);
        }
        __syncthreads();

        if (ck + 2 < NCH) load_stage(ck + 2, ck & 1);
    }

    // --- epilogue ---
    const float* brow = be + (size_t)e * DDIM + n0 + wn;
    float2 bias[8];
#pragma unroll
    for (int ni = 0; ni < 8; ni++)
        bias[ni] = *reinterpret_cast<const float2*>(brow + ni * 8 + 2 * (lane & 3));

#pragma unroll
    for (int mi = 0; mi < 2; mi++)
#pragma unroll
        for (int h = 0; h < 2; h++) {
            int mrow = wm + mi * 16 + (lane >> 2) + h * 8;
            if (m0 + mrow < cnt) {
                int tok = s_tok[mrow];
                float g = s_gate[mrow];
                float* orow = out + (size_t)tok * DDIM + n0 + wn + 2 * (lane & 3);
#pragma unroll
                for (int ni = 0; ni < 8; ni++) {
                    red_v2(orow + ni * 8,
                           g * (acc[mi][ni][h * 2 + 0] + bias[ni].x),
                           g * (acc[mi][ni][h * 2 + 1] + bias[ni].y));
                }
            }
        }
}

// ---------------------------------------------------------------------------
extern "C" void kernel_launch(void* const* d_in, const int* in_sizes, int n_in,
                              void* d_out, int out_size) {
    const float* x  = (const float*)d_in[0];   // [16384, 1024]
    const float* Wg = (const float*)d_in[1];   // [8, 1024]
    const float* bg = (const float*)d_in[2];   // [8]
    const float* We = (const float*)d_in[3];   // [8, 1024, 1024]
    const float* be = (const float*)d_in[4];   // [8, 1024]
    float* out = (float*)d_out;                // [16384, 1024]

    cudaFuncSetAttribute(moe_gemm_kernel,
                         cudaFuncAttributeMaxDynamicSharedMemorySize, SMEM_DYN);

    zero_kernel<<<(T_TOK * DDIM / 4) / 256, 256>>>(out);          // 16384 blocks
    cvt_x_kernel<<<(T_TOK * DDIM / 4) / 256, 256>>>(x);           // 16384 blocks
    cvt_w_kernel<<<(NEXP * DDIM * DDIM / 4) / 256, 256>>>(We);    // 8192 blocks
    gate_kernel<<<T_TOK / 8, 256>>>(x, Wg, bg);

    dim3 grid(DDIM / NT, T_TOK / MT, NEXP);   // (8, 128, 8)
    moe_gemm_kernel<<<grid, 256, SMEM_DYN>>>(be, out);
}

// round 6
// speedup vs baseline: 6.7661x; 1.0458x over previous
#include <cuda_runtime.h>
#include <cuda_fp16.h>
#include <cstdint>

// Problem constants (fixed by the dataset)
#define T_TOK 16384
#define DDIM  1024
#define NEXP  8

// GEMM tiling
#define MT  128
#define NT  128
#define KC  64
#define NCH (DDIM / KC)        // 16 k-chunks
#define NSTAGE 3
#define STAGE_B 32768          // A(16KB) + B(16KB) per stage
#define SMEM_DYN (NSTAGE * STAGE_B) // 96KB

// ---------------------------------------------------------------------------
// Scratch (device globals; allocation is forbidden)
// ---------------------------------------------------------------------------
__device__ int    g_count[NEXP];
__device__ int    g_tok [NEXP][T_TOK];
__device__ float  g_gate[NEXP][T_TOK];
__device__ float  g_logits[(size_t)T_TOK * NEXP];
__device__ __half g_xf[(size_t)T_TOK * DDIM];             // x in fp16
__device__ __half g_wf[(size_t)NEXP * DDIM * DDIM];       // We in fp16

// ---------------------------------------------------------------------------
// PTX helpers (base-ISA only: plain sm_103 target)
// ---------------------------------------------------------------------------
__device__ __forceinline__ uint32_t smem_u32(const void* p) {
    uint32_t a;
    asm("{ .reg .u64 t; cvta.to.shared.u64 t, %1; cvt.u32.u64 %0, t; }" : "=r"(a) : "l"(p));
    return a;
}
__device__ __forceinline__ uint32_t swz(uint32_t o) { return o ^ ((o >> 3) & 0x70); }

__device__ __forceinline__ void cp16(uint32_t dst, const void* src) {
    asm volatile("cp.async.cg.shared.global [%0], [%1], 16;" :: "r"(dst), "l"(src));
}
#define CP_COMMIT() asm volatile("cp.async.commit_group;" ::: "memory")
#define CP_WAIT(n)  asm volatile("cp.async.wait_group %0;" :: "n"(n) : "memory")

__device__ __forceinline__ void ldmx4(uint32_t* r, uint32_t addr) {
    asm volatile("ldmatrix.sync.aligned.m8n8.x4.shared.b16 {%0,%1,%2,%3}, [%4];"
                 : "=r"(r[0]), "=r"(r[1]), "=r"(r[2]), "=r"(r[3]) : "r"(addr));
}

__device__ __forceinline__ void mma16816(float* c, const uint32_t* a, const uint32_t* b) {
    asm volatile("mma.sync.aligned.m16n8k16.row.col.f32.f16.f16.f32 "
                 "{%0,%1,%2,%3}, {%4,%5,%6,%7}, {%8,%9}, {%0,%1,%2,%3};"
                 : "+f"(c[0]), "+f"(c[1]), "+f"(c[2]), "+f"(c[3])
                 : "r"(a[0]), "r"(a[1]), "r"(a[2]), "r"(a[3]), "r"(b[0]), "r"(b[1]));
}

__device__ __forceinline__ void red_v2(float* p, float v0, float v1) {
    asm volatile("red.global.add.v2.f32 [%0], {%1, %2};" :: "l"(p), "f"(v0), "f"(v1) : "memory");
}

// ---------------------------------------------------------------------------
// Kernel 0: zero output + counters
// ---------------------------------------------------------------------------
__global__ void zero_kernel(float* __restrict__ out) {
    int i = blockIdx.x * blockDim.x + threadIdx.x;     // grid exactly covers n4
    reinterpret_cast<float4*>(out)[i] = make_float4(0.f, 0.f, 0.f, 0.f);
    if (blockIdx.x == 0 && threadIdx.x < NEXP) g_count[threadIdx.x] = 0;
}

// ---------------------------------------------------------------------------
// Kernel 1: fused x fp32->fp16 convert + gate logits.
// One block = one token row (1024 elems, 256 threads x float4).
// Wg slices live in registers (L2-broadcast loads), block-reduce 8 logits.
// ---------------------------------------------------------------------------
__global__ void __launch_bounds__(256)
cvt_x_gate_kernel(const float* __restrict__ x,
                  const float* __restrict__ Wg,
                  const float* __restrict__ bg) {
    const int t = blockIdx.x;
    const int i = threadIdx.x;

    float4 v = reinterpret_cast<const float4*>(x + (size_t)t * DDIM)[i];

    __half2* d = reinterpret_cast<__half2*>(g_xf + (size_t)t * DDIM);
    d[i * 2 + 0] = __floats2half2_rn(v.x, v.y);
    d[i * 2 + 1] = __floats2half2_rn(v.z, v.w);

    float acc[NEXP];
#pragma unroll
    for (int e = 0; e < NEXP; e++) {
        float4 w = reinterpret_cast<const float4*>(Wg + e * DDIM)[i];
        acc[e] = v.x * w.x + v.y * w.y + v.z * w.z + v.w * w.w;
    }
#pragma unroll
    for (int off = 16; off > 0; off >>= 1)
#pragma unroll
        for (int e = 0; e < NEXP; e++)
            acc[e] += __shfl_xor_sync(0xFFFFFFFFu, acc[e], off);

    __shared__ float red[8][NEXP];
    const int warp = i >> 5, lane = i & 31;
    if (lane == 0)
#pragma unroll
        for (int e = 0; e < NEXP; e++) red[warp][e] = acc[e];
    __syncthreads();

    if (i < NEXP) {
        float s = bg[i];
#pragma unroll
        for (int w = 0; w < 8; w++) s += red[w][i];
        g_logits[(size_t)t * NEXP + i] = s;
    }
}

// ---------------------------------------------------------------------------
// Kernel 2: top-2 + softmax + block-aggregated compaction.
// 64 blocks x 256 threads, one token per thread.
// ---------------------------------------------------------------------------
__global__ void __launch_bounds__(256)
topk_kernel() {
    const int tid = threadIdx.x;
    const int t = blockIdx.x * 256 + tid;

    __shared__ int cnt_s[NEXP];
    __shared__ int base_s[NEXP];
    if (tid < NEXP) cnt_s[tid] = 0;
    __syncthreads();

    float l[NEXP];
    float4 l0 = reinterpret_cast<const float4*>(g_logits + (size_t)t * NEXP)[0];
    float4 l1 = reinterpret_cast<const float4*>(g_logits + (size_t)t * NEXP)[1];
    l[0]=l0.x; l[1]=l0.y; l[2]=l0.z; l[3]=l0.w;
    l[4]=l1.x; l[5]=l1.y; l[6]=l1.z; l[7]=l1.w;

    int i0 = 0;
#pragma unroll
    for (int e = 1; e < NEXP; e++) if (l[e] > l[i0]) i0 = e;
    int i1 = (i0 == 0) ? 1 : 0;
#pragma unroll
    for (int e = 0; e < NEXP; e++) {
        if (e == i0) continue;
        if (l[e] > l[i1]) i1 = e;
    }
    float m  = fmaxf(l[i0], l[i1]);
    float e0 = __expf(l[i0] - m);
    float e1 = __expf(l[i1] - m);
    float inv = 1.f / (e0 + e1);

    int p0 = atomicAdd(&cnt_s[i0], 1);
    int p1 = atomicAdd(&cnt_s[i1], 1);
    __syncthreads();
    if (tid < NEXP) base_s[tid] = atomicAdd(&g_count[tid], cnt_s[tid]);
    __syncthreads();

    int q0 = base_s[i0] + p0;
    g_tok[i0][q0] = t; g_gate[i0][q0] = e0 * inv;
    int q1 = base_s[i1] + p1;
    g_tok[i1][q1] = t; g_gate[i1][q1] = e1 * inv;
}

// ---------------------------------------------------------------------------
// Kernel 0b: We fp32 -> fp16
// ---------------------------------------------------------------------------
__global__ void cvt_w_kernel(const float* __restrict__ w) {
    int i = blockIdx.x * blockDim.x + threadIdx.x;
    float4 v = reinterpret_cast<const float4*>(w)[i];
    __half2* d = reinterpret_cast<__half2*>(g_wf);
    d[i * 2 + 0] = __floats2half2_rn(v.x, v.y);
    d[i * 2 + 1] = __floats2half2_rn(v.z, v.w);
}

// ---------------------------------------------------------------------------
// Kernel 3: fp16 HMMA expert GEMM, 128x128 tile, 3-stage cp.async pipeline,
// one __syncthreads per k-chunk. Epilogue via red.global.add.v2.f32.
// ---------------------------------------------------------------------------
__global__ void __launch_bounds__(256, 2)
moe_gemm_kernel(const float* __restrict__ be, float* __restrict__ out) {
    const int e   = blockIdx.z;
    const int cnt = g_count[e];
    const int m0  = blockIdx.y * MT;
    if (m0 >= cnt) return;
    const int n0  = blockIdx.x * NT;

    extern __shared__ __align__(128) char smem[];
    const uint32_t sbase = smem_u32(smem);

    __shared__ int   s_tok[MT];
    __shared__ float s_gate[MT];

    const int tid  = threadIdx.x;
    const int wid  = tid >> 5, lane = tid & 31;
    const int wm   = (wid & 3) * 32;     // warp row offset in tile
    const int wn   = (wid >> 2) * 64;    // warp col offset in tile

    if (tid < MT) {
        int m = m0 + tid;
        s_tok[tid]  = (m < cnt) ? g_tok[e][m]  : 0;
        s_gate[tid] = (m < cnt) ? g_gate[e][m] : 0.f;
    }
    __syncthreads();

    const size_t wbase = ((size_t)e << 20) + (size_t)n0 * DDIM;  // e*1024*1024

    auto load_stage = [&](int ck, int s) {
        const int k0 = ck * KC;
        const uint32_t sA = sbase + s * STAGE_B;
        const uint32_t sB = sA + 16384;
#pragma unroll
        for (int i = 0; i < 4; i++) {
            int u = tid + i * 256;               // 0..1023
            int row = u >> 3, c = u & 7;         // 128 rows x 8 16B-chunks
            const __half* src = &g_xf[(size_t)s_tok[row] * DDIM + k0 + c * 8];
            cp16(sA + swz((uint32_t)(row * 128 + c * 16)), src);
        }
#pragma unroll
        for (int i = 0; i < 4; i++) {
            int u = tid + i * 256;
            int row = u >> 3, c = u & 7;
            const __half* src = &g_wf[wbase + (size_t)row * DDIM + k0 + c * 8];
            cp16(sB + swz((uint32_t)(row * 128 + c * 16)), src);
        }
        CP_COMMIT();
    };

    float acc[2][8][4];
#pragma unroll
    for (int mi = 0; mi < 2; mi++)
#pragma unroll
        for (int ni = 0; ni < 8; ni++)
#pragma unroll
            for (int q = 0; q < 4; q++) acc[mi][ni][q] = 0.f;

    load_stage(0, 0);
    load_stage(1, 1);

#pragma unroll 1
    for (int ck = 0; ck < NCH; ck++) {
        if (ck + 1 < NCH) { CP_WAIT(1); } else { CP_WAIT(0); }
        __syncthreads();
        // Slot (ck+2)%3 was consumed at iteration ck-1; the barrier above
        // guarantees every warp has finished those MMAs -> safe to refill now.
        if (ck + 2 < NCH) load_stage(ck + 2, (ck + 2) % NSTAGE);

        const uint32_t sA = sbase + (ck % NSTAGE) * STAGE_B;
        const uint32_t sB = sA + 16384;

#pragma unroll
        for (int ks = 0; ks < 4; ks++) {
            uint32_t a[2][4];
#pragma unroll
            for (int mi = 0; mi < 2; mi++) {
                int row = wm + mi * 16 + (lane & 15);
                ldmx4(a[mi], sA + swz((uint32_t)(row * 128 + (ks * 2 + (lane >> 4)) * 16)));
            }
            uint32_t b[4][4];
#pragma unroll
            for (int pi = 0; pi < 4; pi++) {
                int n = wn + pi * 16 + ((lane >> 4) << 3) + (lane & 7);
                ldmx4(b[pi], sB + swz((uint32_t)(n * 128 + (ks * 2 + ((lane >> 3) & 1)) * 16)));
            }
#pragma unroll
            for (int mi = 0; mi < 2; mi++)
#pragma unroll
                for (int ni = 0; ni < 8; ni++)
                    mma16816(acc[mi][ni], a[mi], &b[ni >> 1][(ni & 1) * 2]);
        }
    }

    // --- epilogue ---
    const float* brow = be + (size_t)e * DDIM + n0 + wn;
    float2 bias[8];
#pragma unroll
    for (int ni = 0; ni < 8; ni++)
        bias[ni] = *reinterpret_cast<const float2*>(brow + ni * 8 + 2 * (lane & 3));

#pragma unroll
    for (int mi = 0; mi < 2; mi++)
#pragma unroll
        for (int h = 0; h < 2; h++) {
            int mrow = wm + mi * 16 + (lane >> 2) + h * 8;
            if (m0 + mrow < cnt) {
                int tok = s_tok[mrow];
                float g = s_gate[mrow];
                float* orow = out + (size_t)tok * DDIM + n0 + wn + 2 * (lane & 3);
#pragma unroll
                for (int ni = 0; ni < 8; ni++) {
                    red_v2(orow + ni * 8,
                           g * (acc[mi][ni][h * 2 + 0] + bias[ni].x),
                           g * (acc[mi][ni][h * 2 + 1] + bias[ni].y));
                }
            }
        }
}

// ---------------------------------------------------------------------------
extern "C" void kernel_launch(void* const* d_in, const int* in_sizes, int n_in,
                              void* d_out, int out_size) {
    const float* x  = (const float*)d_in[0];   // [16384, 1024]
    const float* Wg = (const float*)d_in[1];   // [8, 1024]
    const float* bg = (const float*)d_in[2];   // [8]
    const float* We = (const float*)d_in[3];   // [8, 1024, 1024]
    const float* be = (const float*)d_in[4];   // [8, 1024]
    float* out = (float*)d_out;                // [16384, 1024]

    cudaFuncSetAttribute(moe_gemm_kernel,
                         cudaFuncAttributeMaxDynamicSharedMemorySize, SMEM_DYN);

    zero_kernel<<<(T_TOK * DDIM / 4) / 256, 256>>>(out);          // 16384 blocks
    cvt_w_kernel<<<(NEXP * DDIM * DDIM / 4) / 256, 256>>>(We);    // 8192 blocks
    cvt_x_gate_kernel<<<T_TOK, 256>>>(x, Wg, bg);
    topk_kernel<<<T_TOK / 256, 256>>>();

    dim3 grid(DDIM / NT, T_TOK / MT, NEXP);   // (8, 128, 8)
    moe_gemm_kernel<<<grid, 256, SMEM_DYN>>>(be, out);
}